// round 2
// baseline (speedup 1.0000x reference)
#include <cuda_runtime.h>
#include <cuda_bf16.h>

// ---------------------------------------------------------------------------
// Problem constants (fixed by setup_inputs)
// ---------------------------------------------------------------------------
#define NN 250000
#define EE 1000000
#define BB 500
#define FD 78

typedef unsigned long long u64;

// ---------------------------------------------------------------------------
// Scratch (device globals: no allocation allowed)
// ---------------------------------------------------------------------------
__device__ float    g_bufA[NN * 156];        // 156 MB
__device__ float    g_bufB[NN * 156];        // 156 MB
__device__ float    g_dinv[NN];
__device__ int      g_cnt[NN];
__device__ int      g_rowptr[NN + 1];
__device__ int      g_cursor[NN];
__device__ int      g_csrc[EE];
__device__ int      g_bsum[512];
__device__ int      g_boff[512];
__device__ unsigned g_pool[BB * 312];
__device__ float    g_S1[BB * 1024];
__device__ float    g_S2[BB * 512];
__device__ float    g_xc[BB * 256];
__device__ float    g_G[BB * 256 * 26];      // [b][o*8+k][l]
__device__ float    g_Cbuf[BB * 3872];

// ---------------------------------------------------------------------------
// f32x2 packed FMA (sm_100+): d = a*b + c elementwise on packed fp32 pairs.
// Exact fp32 semantics per lane; doubles FMA throughput vs scalar FFMA.
// ---------------------------------------------------------------------------
__device__ __forceinline__ u64 ffma2(u64 a, u64 b, u64 c) {
    u64 d;
    asm("fma.rn.f32x2 %0, %1, %2, %3;" : "=l"(d) : "l"(a), "l"(b), "l"(c));
    return d;
}
__device__ __forceinline__ u64 pack2(float x, float y) {
    u64 r;
    asm("mov.b64 %0, {%1, %2};" : "=l"(r) : "f"(x), "f"(y));
    return r;
}
__device__ __forceinline__ float lo32(u64 v) { return __uint_as_float((unsigned)(v & 0xffffffffull)); }
__device__ __forceinline__ float hi32(u64 v) { return __uint_as_float((unsigned)(v >> 32)); }

// ---------------------------------------------------------------------------
// Small utility kernels
// ---------------------------------------------------------------------------
__global__ void k_zero_int(int* p, int n) {
    int i = blockIdx.x * blockDim.x + threadIdx.x;
    if (i < n) p[i] = 0;
}
__global__ void k_zero_u32(unsigned* p, int n) {
    int i = blockIdx.x * blockDim.x + threadIdx.x;
    if (i < n) p[i] = 0u;
}
__global__ void k_zero_f32(float* p, int n) {
    int i = blockIdx.x * blockDim.x + threadIdx.x;
    if (i < n) p[i] = 0.f;
}

// ---------------------------------------------------------------------------
// CSR build: count -> scan -> offsets -> fill
// ---------------------------------------------------------------------------
__global__ void k_count(const int* __restrict__ dst, int e) {
    int i = blockIdx.x * blockDim.x + threadIdx.x;
    if (i < e) atomicAdd(&g_cnt[dst[i]], 1);
}

__global__ void k_scan1(int n) {
    __shared__ int s[512];
    int t = threadIdx.x;
    int i = blockIdx.x * 512 + t;
    int v = (i < n) ? g_cnt[i] : 0;
    s[t] = v;
    __syncthreads();
    for (int off = 1; off < 512; off <<= 1) {
        int tmp = (t >= off) ? s[t - off] : 0;
        __syncthreads();
        s[t] += tmp;
        __syncthreads();
    }
    if (i < n) g_rowptr[i] = s[t] - v;   // exclusive within block
    if (t == 511) g_bsum[blockIdx.x] = s[511];
}

__global__ void k_scan2(int nb) {
    __shared__ int s[512];
    int t = threadIdx.x;
    int v = (t < nb) ? g_bsum[t] : 0;
    s[t] = v;
    __syncthreads();
    for (int off = 1; off < 512; off <<= 1) {
        int tmp = (t >= off) ? s[t - off] : 0;
        __syncthreads();
        s[t] += tmp;
        __syncthreads();
    }
    if (t < nb) g_boff[t] = s[t] - v;    // exclusive
}

__global__ void k_scan3(int n, int e) {
    int i = blockIdx.x * blockDim.x + threadIdx.x;
    if (i < n) {
        int v = g_rowptr[i] + g_boff[i >> 9];
        g_rowptr[i] = v;
        g_cursor[i] = v;
        g_dinv[i] = rsqrtf((float)g_cnt[i] + 1.0f);   // degree + self-loop
    }
    if (i == 0) g_rowptr[n] = e;
}

__global__ void k_fill(const int* __restrict__ src, const int* __restrict__ dst, int e) {
    int i = blockIdx.x * blockDim.x + threadIdx.x;
    if (i < e) {
        int d = dst[i];
        int p = atomicAdd(&g_cursor[d], 1);
        g_csrc[p] = src[i];
    }
}

// ---------------------------------------------------------------------------
// Aggregation: out[v] = dinv[v] * ( s(v)*in[v] + sum_{u in N(v)} s(u)*in[u] )
// PRESCALED: input rows already carry their dinv factor (s == 1)
// One warp per node; F columns strided over lanes.
// ---------------------------------------------------------------------------
template <int F, bool PRESCALED>
__global__ void k_agg(const float* __restrict__ in, float* __restrict__ out, int n) {
    int warp = (blockIdx.x * blockDim.x + threadIdx.x) >> 5;
    int lane = threadIdx.x & 31;
    if (warp >= n) return;
    const int v = warp;
    constexpr int R = (F + 31) / 32;
    float dv = g_dinv[v];
    float ss = PRESCALED ? 1.f : dv;
    float acc[R];
#pragma unroll
    for (int i = 0; i < R; i++) {
        int f = lane + 32 * i;
        acc[i] = (f < F) ? in[(size_t)v * F + f] * ss : 0.f;
    }
    int e0 = g_rowptr[v], e1 = g_rowptr[v + 1];
    for (int e = e0; e < e1; e++) {
        int u = g_csrc[e];
        float us = PRESCALED ? 1.f : g_dinv[u];
#pragma unroll
        for (int i = 0; i < R; i++) {
            int f = lane + 32 * i;
            if (f < F) acc[i] += in[(size_t)u * F + f] * us;
        }
    }
#pragma unroll
    for (int i = 0; i < R; i++) {
        int f = lane + 32 * i;
        if (f < F) out[(size_t)v * F + f] = acc[i] * dv;
    }
}

// ---------------------------------------------------------------------------
// f32x2 SIMT GEMM: C[NR,M] = A[NR,K] @ W[K,M]   (all row-major)
// BM=128, BN=64, BK=16, 256 threads, 8x4 per-thread microtile computed as
// 4 row-PAIRS x 4 cols of packed fma.rn.f32x2 (FFMA2) -> 2x FFMA throughput.
// A pairs come straight from shared (adjacent rows in As are pair lanes);
// B is stored DUPLICATED {v,v} in shared so no pack instructions in the loop.
// Epilogues:
//  0 STORE      : C = acc + bias
//  1 RELU       : C = relu(acc + bias)
//  2 RELU_DINV  : C = relu(acc + bias) * dinv[row]
//  3 MAXPOOL    : atomicMax(pool[batch[row]*M + col], bits(relu(acc+bias)))
//  4 ADD_ATOMIC : atomicAdd(C, acc + (z==0 ? bias : 0))   (split-K)
// ---------------------------------------------------------------------------
#define GBM 128
#define GBN 64
#define GBK 16

template <int EPI>
__global__ __launch_bounds__(256)
void k_gemm(const float* __restrict__ A, int lda,
            const float* __restrict__ W, int ldb,
            float* __restrict__ C, int ldc,
            int NR, int M, int K,
            const float* __restrict__ bias,
            const float* __restrict__ dinv,
            const int* __restrict__ batch,
            unsigned* __restrict__ pool,
            int kChunk) {
    // row pitches chosen so every row start is 16B-aligned (132*4 = 528 = 33*16)
    __shared__ float As[GBK][GBM + 4];
    __shared__ float Bs[GBK][2 * GBN + 4];   // duplicated pairs: [2n]=[2n+1]=W[k][n]

    const int m0 = blockIdx.x * GBM;
    const int n0 = blockIdx.y * GBN;
    const int kb = blockIdx.z * kChunk;
    const int ke = min(K, kb + kChunk);

    const int tid = threadIdx.x;
    const int tN = tid & 15;   // 16 col groups (4 cols each)
    const int tM = tid >> 4;   // 16 row groups (8 rows = 4 pairs each)

    u64 acc[4][4];             // [row-pair][col], each holds 2 fp32 (rows 2p, 2p+1)
#pragma unroll
    for (int p = 0; p < 4; p++)
#pragma unroll
        for (int j = 0; j < 4; j++) acc[p][j] = 0ull;

    for (int k0 = kb; k0 < ke; k0 += GBK) {
#pragma unroll
        for (int r = 0; r < 8; r++) {
            int idx = tid + r * 256;
            int mm = idx >> 4, kk = idx & 15;
            int gm = m0 + mm, gk = k0 + kk;
            As[kk][mm] = (gm < NR && gk < ke) ? A[(size_t)gm * lda + gk] : 0.f;
        }
#pragma unroll
        for (int r = 0; r < 4; r++) {
            int idx = tid + r * 256;
            int kk = idx >> 6, nn = idx & 63;
            int gk = k0 + kk, gn = n0 + nn;
            float v = (gk < ke && gn < M) ? W[(size_t)gk * ldb + gn] : 0.f;
            *reinterpret_cast<u64*>(&Bs[kk][2 * nn]) = pack2(v, v);
        }
        __syncthreads();
#pragma unroll
        for (int kk = 0; kk < GBK; kk++) {
            // 8 A rows as 4 packed pairs (two lds.128)
            ulonglong2 a01 = *reinterpret_cast<const ulonglong2*>(&As[kk][tM * 8]);
            ulonglong2 a23 = *reinterpret_cast<const ulonglong2*>(&As[kk][tM * 8 + 4]);
            // 4 duplicated B pairs (two lds.128)
            ulonglong2 b01 = *reinterpret_cast<const ulonglong2*>(&Bs[kk][tN * 8]);
            ulonglong2 b23 = *reinterpret_cast<const ulonglong2*>(&Bs[kk][tN * 8 + 4]);
            u64 ap[4] = {a01.x, a01.y, a23.x, a23.y};
            u64 bp[4] = {b01.x, b01.y, b23.x, b23.y};
#pragma unroll
            for (int p = 0; p < 4; p++)
#pragma unroll
                for (int j = 0; j < 4; j++)
                    acc[p][j] = ffma2(ap[p], bp[j], acc[p][j]);
        }
        __syncthreads();
    }

#pragma unroll
    for (int p = 0; p < 4; p++) {
#pragma unroll
        for (int half = 0; half < 2; half++) {
            int row = m0 + tM * 8 + 2 * p + half;
            if (row >= NR) continue;
#pragma unroll
            for (int j = 0; j < 4; j++) {
                int col = n0 + tN * 4 + j;
                if (col >= M) continue;
                float v = half ? hi32(acc[p][j]) : lo32(acc[p][j]);
                if (EPI == 0) {
                    if (bias) v += bias[col];
                    C[(size_t)row * ldc + col] = v;
                } else if (EPI == 1) {
                    v += bias[col];
                    C[(size_t)row * ldc + col] = fmaxf(v, 0.f);
                } else if (EPI == 2) {
                    v += bias[col];
                    C[(size_t)row * ldc + col] = fmaxf(v, 0.f) * dinv[row];
                } else if (EPI == 3) {
                    v = fmaxf(v + bias[col], 0.f);
                    atomicMax(&pool[(size_t)batch[row] * M + col], __float_as_uint(v));
                } else {  // 4
                    if (blockIdx.z == 0 && bias) v += bias[col];
                    atomicAdd(&C[(size_t)row * ldc + col], v);
                }
            }
        }
    }
}

// ---------------------------------------------------------------------------
// Protein branch: G[b,o,k,l] = sum_i conv_w[o,i,k] * [target[b,i] == l]
// One block per graph, 256 threads = (o,k) pairs, private 26-bin shared accs.
// ---------------------------------------------------------------------------
__global__ void k_gbuild(const int* __restrict__ target, const float* __restrict__ conv_w) {
    __shared__ int   ts[1000];
    __shared__ float acc[256 * 26];
    const int b = blockIdx.x, tid = threadIdx.x;
    for (int i = tid; i < 1000; i += 256) ts[i] = target[b * 1000 + i];
#pragma unroll
    for (int l = 0; l < 26; l++) acc[tid * 26 + l] = 0.f;
    __syncthreads();
    const int o = tid >> 3, k = tid & 7;
    const float* wp = conv_w + o * 8000 + k;
    for (int i = 0; i < 1000; i++) {
        acc[tid * 26 + ts[i]] += wp[i * 8];
    }
    float* g = g_G + (size_t)b * 6656 + tid * 26;
#pragma unroll
    for (int l = 0; l < 26; l++) g[l] = acc[tid * 26 + l];
}

// c[b,o,h] = conv_b[o] + sum_{k,l} G[b,o,k,l] * emb[l, h+k]
__global__ void k_cconv(const float* __restrict__ emb, const float* __restrict__ conv_b) {
    __shared__ float Gs[6656];
    __shared__ float Es[26 * 128];
    const int b = blockIdx.x, tid = threadIdx.x;
    for (int i = tid; i < 6656; i += 256) Gs[i] = g_G[(size_t)b * 6656 + i];
    for (int i = tid; i < 26 * 128; i += 256) Es[i] = emb[i];
    __syncthreads();
    for (int idx = tid; idx < 3872; idx += 256) {
        int o = idx / 121, h = idx % 121;
        float s = conv_b[o];
#pragma unroll
        for (int k = 0; k < 8; k++)
#pragma unroll
            for (int l = 0; l < 26; l++)
                s += Gs[(o * 8 + k) * 26 + l] * Es[l * 128 + h + k];
        g_Cbuf[(size_t)b * 3872 + idx] = s;
    }
}

// ---------------------------------------------------------------------------
// Final projection: out[r] = dot(S2[r,:512], out_w) + out_b. One warp per row.
// ---------------------------------------------------------------------------
__global__ void k_out(const float* __restrict__ ow, const float* __restrict__ ob,
                      float* __restrict__ out, int rows) {
    int row = blockIdx.x * 8 + (threadIdx.x >> 5);
    int lane = threadIdx.x & 31;
    if (row >= rows) return;
    float s = 0.f;
    for (int j = lane; j < 512; j += 32) s += g_S2[row * 512 + j] * ow[j];
#pragma unroll
    for (int off = 16; off; off >>= 1) s += __shfl_down_sync(0xffffffffu, s, off);
    if (lane == 0) out[row] = s + ob[0];
}

// ---------------------------------------------------------------------------
// Launch
// ---------------------------------------------------------------------------
extern "C" void kernel_launch(void* const* d_in, const int* in_sizes, int n_in,
                              void* d_out, int out_size) {
    const float* x       = (const float*)d_in[0];
    const int*   ei      = (const int*)d_in[1];      // [2, E]: row0 src, row1 dst
    const int*   batch   = (const int*)d_in[2];
    const int*   target  = (const int*)d_in[3];
    const float* W1      = (const float*)d_in[4];
    const float* b1      = (const float*)d_in[5];
    const float* W2      = (const float*)d_in[6];
    const float* b2      = (const float*)d_in[7];
    const float* W3      = (const float*)d_in[8];
    const float* b3      = (const float*)d_in[9];
    const float* fcg1_w  = (const float*)d_in[10];
    const float* fcg1_b  = (const float*)d_in[11];
    const float* fcg2_w  = (const float*)d_in[12];
    const float* fcg2_b  = (const float*)d_in[13];
    const float* emb     = (const float*)d_in[14];
    const float* conv_w  = (const float*)d_in[15];
    const float* conv_b  = (const float*)d_in[16];
    const float* fcxt_w  = (const float*)d_in[17];
    const float* fcxt_b  = (const float*)d_in[18];
    const float* fc1_w   = (const float*)d_in[19];
    const float* fc1_b   = (const float*)d_in[20];
    const float* fc2_w   = (const float*)d_in[21];
    const float* fc2_b   = (const float*)d_in[22];
    const float* out_w   = (const float*)d_in[23];
    const float* out_b   = (const float*)d_in[24];
    float* out = (float*)d_out;

    float *bufA, *bufB, *dinv, *S1, *S2, *xc, *Cbuf;
    int *cnt;
    unsigned* pool;
    cudaGetSymbolAddress((void**)&bufA, g_bufA);
    cudaGetSymbolAddress((void**)&bufB, g_bufB);
    cudaGetSymbolAddress((void**)&dinv, g_dinv);
    cudaGetSymbolAddress((void**)&cnt,  g_cnt);
    cudaGetSymbolAddress((void**)&pool, g_pool);
    cudaGetSymbolAddress((void**)&S1,   g_S1);
    cudaGetSymbolAddress((void**)&S2,   g_S2);
    cudaGetSymbolAddress((void**)&xc,   g_xc);
    cudaGetSymbolAddress((void**)&Cbuf, g_Cbuf);

    const int N = NN, E = EE, B = BB;
    const int NB = (N + 511) / 512;               // 489 scan blocks
    const int MG = (N + GBM - 1) / GBM;           // 1954 row blocks

    // ---- CSR + dinv ----
    k_zero_int<<<(N + 255) / 256, 256>>>(cnt, N);
    k_count<<<(E + 255) / 256, 256>>>(ei + E, E);
    k_scan1<<<NB, 512>>>(N);
    k_scan2<<<1, 512>>>(NB);
    k_scan3<<<(N + 255) / 256, 256>>>(N, E);
    k_fill<<<(E + 255) / 256, 256>>>(ei, ei + E, E);

    // ---- GCN layers (aggregate-then-GEMM) ----
    k_agg<78, false><<<N / 8, 256>>>(x, bufA, N);
    k_gemm<2><<<dim3(MG, 2), 256>>>(bufA, 78, W1, 78, bufB, 78, N, 78, 78,
                                    b1, dinv, nullptr, nullptr, 78);
    k_agg<78, true><<<N / 8, 256>>>(bufB, bufA, N);
    k_gemm<2><<<dim3(MG, 3), 256>>>(bufA, 78, W2, 156, bufB, 156, N, 156, 78,
                                    b2, dinv, nullptr, nullptr, 78);
    k_agg<156, true><<<N / 8, 256>>>(bufB, bufA, N);
    k_zero_u32<<<(B * 312 + 255) / 256, 256>>>(pool, B * 312);
    k_gemm<3><<<dim3(MG, 5), 256>>>(bufA, 156, W3, 312, nullptr, 312, N, 312, 156,
                                    b3, nullptr, batch, pool, 156);

    // ---- graph head ----
    k_gemm<1><<<dim3(4, 16), 256>>>((const float*)pool, 312, fcg1_w, 1024, S1, 1024,
                                    B, 1024, 312, fcg1_b, nullptr, nullptr, nullptr, 312);
    k_zero_f32<<<(B * 256 + 255) / 256, 256>>>(xc, B * 256);
    k_gemm<0><<<dim3(4, 2), 256>>>(S1, 1024, fcg2_w, 128, xc, 256,
                                   B, 128, 1024, fcg2_b, nullptr, nullptr, nullptr, 1024);

    // ---- protein branch (alphabet-factored conv) ----
    k_gbuild<<<B, 256>>>(target, conv_w);
    k_cconv<<<B, 256>>>(emb, conv_b);
    k_gemm<4><<<dim3(4, 2, 16), 256>>>(Cbuf, 3872, fcxt_w, 128, xc + 128, 256,
                                       B, 128, 3872, fcxt_b, nullptr, nullptr, nullptr, 242);

    // ---- fusion head ----
    k_gemm<1><<<dim3(4, 16), 256>>>(xc, 256, fc1_w, 1024, S1, 1024,
                                    B, 1024, 256, fc1_b, nullptr, nullptr, nullptr, 256);
    k_gemm<1><<<dim3(4, 8), 256>>>(S1, 1024, fc2_w, 512, S2, 512,
                                   B, 512, 1024, fc2_b, nullptr, nullptr, nullptr, 1024);
    k_out<<<(B + 7) / 8, 256>>>(out_w, out_b, out, B);
}

// round 3
// speedup vs baseline: 1.1403x; 1.1403x over previous
#include <cuda_runtime.h>
#include <cuda_bf16.h>

// ---------------------------------------------------------------------------
// Problem constants (fixed by setup_inputs)
// ---------------------------------------------------------------------------
#define NN 250000
#define EE 1000000
#define BB 500
#define FD 78

// ---------------------------------------------------------------------------
// Scratch (device globals: no allocation allowed)
// ---------------------------------------------------------------------------
__device__ float    g_bufA[NN * 156];        // 156 MB
__device__ float    g_bufB[NN * 156];        // 156 MB
__device__ float    g_dinv[NN];
__device__ int      g_cnt[NN];
__device__ int      g_rowptr[NN + 1];
__device__ int      g_cursor[NN];
__device__ int      g_csrc[EE];
__device__ int      g_bsum[512];
__device__ int      g_boff[512];
__device__ unsigned g_pool[BB * 312];
__device__ float    g_S1[BB * 1024];
__device__ float    g_S2[BB * 512];
__device__ float    g_xc[BB * 256];
__device__ float    g_G[BB * 256 * 26];      // [b][o*8+k][l]
__device__ float    g_Cbuf[BB * 3872];

// ---------------------------------------------------------------------------
// Small utility kernels
// ---------------------------------------------------------------------------
__global__ void k_zero_int(int* p, int n) {
    int i = blockIdx.x * blockDim.x + threadIdx.x;
    if (i < n) p[i] = 0;
}
__global__ void k_zero_u32(unsigned* p, int n) {
    int i = blockIdx.x * blockDim.x + threadIdx.x;
    if (i < n) p[i] = 0u;
}
__global__ void k_zero_f32(float* p, int n) {
    int i = blockIdx.x * blockDim.x + threadIdx.x;
    if (i < n) p[i] = 0.f;
}

// ---------------------------------------------------------------------------
// CSR build: count -> scan -> offsets -> fill
// ---------------------------------------------------------------------------
__global__ void k_count(const int* __restrict__ dst, int e) {
    int i = blockIdx.x * blockDim.x + threadIdx.x;
    if (i < e) atomicAdd(&g_cnt[dst[i]], 1);
}

__global__ void k_scan1(int n) {
    __shared__ int s[512];
    int t = threadIdx.x;
    int i = blockIdx.x * 512 + t;
    int v = (i < n) ? g_cnt[i] : 0;
    s[t] = v;
    __syncthreads();
    for (int off = 1; off < 512; off <<= 1) {
        int tmp = (t >= off) ? s[t - off] : 0;
        __syncthreads();
        s[t] += tmp;
        __syncthreads();
    }
    if (i < n) g_rowptr[i] = s[t] - v;   // exclusive within block
    if (t == 511) g_bsum[blockIdx.x] = s[511];
}

__global__ void k_scan2(int nb) {
    __shared__ int s[512];
    int t = threadIdx.x;
    int v = (t < nb) ? g_bsum[t] : 0;
    s[t] = v;
    __syncthreads();
    for (int off = 1; off < 512; off <<= 1) {
        int tmp = (t >= off) ? s[t - off] : 0;
        __syncthreads();
        s[t] += tmp;
        __syncthreads();
    }
    if (t < nb) g_boff[t] = s[t] - v;    // exclusive
}

__global__ void k_scan3(int n, int e) {
    int i = blockIdx.x * blockDim.x + threadIdx.x;
    if (i < n) {
        int v = g_rowptr[i] + g_boff[i >> 9];
        g_rowptr[i] = v;
        g_cursor[i] = v;
        g_dinv[i] = rsqrtf((float)g_cnt[i] + 1.0f);   // degree + self-loop
    }
    if (i == 0) g_rowptr[n] = e;
}

__global__ void k_fill(const int* __restrict__ src, const int* __restrict__ dst, int e) {
    int i = blockIdx.x * blockDim.x + threadIdx.x;
    if (i < e) {
        int d = dst[i];
        int p = atomicAdd(&g_cursor[d], 1);
        g_csrc[p] = src[i];
    }
}

// ---------------------------------------------------------------------------
// Aggregation: out[v] = dinv[v] * ( s(v)*in[v] + sum_{u in N(v)} s(u)*in[u] )
// PRESCALED: input rows already carry their dinv factor (s == 1)
// One warp per node; F columns strided over lanes.
// ---------------------------------------------------------------------------
template <int F, bool PRESCALED>
__global__ void k_agg(const float* __restrict__ in, float* __restrict__ out, int n) {
    int warp = (blockIdx.x * blockDim.x + threadIdx.x) >> 5;
    int lane = threadIdx.x & 31;
    if (warp >= n) return;
    const int v = warp;
    constexpr int R = (F + 31) / 32;
    float dv = g_dinv[v];
    float ss = PRESCALED ? 1.f : dv;
    float acc[R];
#pragma unroll
    for (int i = 0; i < R; i++) {
        int f = lane + 32 * i;
        acc[i] = (f < F) ? in[(size_t)v * F + f] * ss : 0.f;
    }
    int e0 = g_rowptr[v], e1 = g_rowptr[v + 1];
    for (int e = e0; e < e1; e++) {
        int u = g_csrc[e];
        float us = PRESCALED ? 1.f : g_dinv[u];
#pragma unroll
        for (int i = 0; i < R; i++) {
            int f = lane + 32 * i;
            if (f < F) acc[i] += in[(size_t)u * F + f] * us;
        }
    }
#pragma unroll
    for (int i = 0; i < R; i++) {
        int f = lane + 32 * i;
        if (f < F) out[(size_t)v * F + f] = acc[i] * dv;
    }
}

// ---------------------------------------------------------------------------
// TF32 tensor-core GEMM: C[NR,M] = A[NR,K] @ W[K,M]  (row-major, fp32 in/out)
// Block tile 64(M) x 128(N) x 32(K). 8 warps -> warp tile 32x32 -> 2x4
// m16n8k8 tf32 MMAs per k-step. Bank-conflict-free shared layouts:
//   As[m][k]  pitch 36 (frag-read addr == lane mod 32 banks)
//   Bs[k][n]  pitch 136 (8k+n covers all banks)
// Epilogues:
//  2 RELU_DINV : C = relu(acc + bias) * dinv[row]
//  3 MAXPOOL   : atomicMax(pool[batch[row]*ldc + col], bits(relu(acc+bias)))
// ---------------------------------------------------------------------------
__device__ __forceinline__ unsigned f2tf32(float v) {
    unsigned u;
    asm("cvt.rna.tf32.f32 %0, %1;" : "=r"(u) : "f"(v));
    return u;
}
__device__ __forceinline__ void mma_tf32(float c[4], const unsigned a[4], const unsigned b[2]) {
    asm volatile(
        "mma.sync.aligned.m16n8k8.row.col.f32.tf32.tf32.f32 "
        "{%0,%1,%2,%3}, {%4,%5,%6,%7}, {%8,%9}, {%0,%1,%2,%3};"
        : "+f"(c[0]), "+f"(c[1]), "+f"(c[2]), "+f"(c[3])
        : "r"(a[0]), "r"(a[1]), "r"(a[2]), "r"(a[3]), "r"(b[0]), "r"(b[1]));
}

template <int EPI>
__global__ __launch_bounds__(256)
void k_tc(const float* __restrict__ A, int lda,
          const float* __restrict__ W, int ldb,
          float* __restrict__ C, int ldc,
          int NR, int M, int K,
          const float* __restrict__ bias,
          const float* __restrict__ dinv,
          const int* __restrict__ batch,
          unsigned* __restrict__ pool) {
    __shared__ unsigned As[64][36];    // m-major tf32
    __shared__ unsigned Bs[32][136];   // k-major tf32

    const int m0 = blockIdx.x * 64;
    const int n0 = blockIdx.y * 128;
    const int tid  = threadIdx.x;
    const int wid  = tid >> 5;
    const int lane = tid & 31;
    const int wm = (wid & 1) * 32;     // warp row offset in block
    const int wn = (wid >> 1) * 32;    // warp col offset in block
    const int g  = lane >> 2;          // groupID
    const int tg = lane & 3;           // thread-in-group

    float acc[2][4][4];
#pragma unroll
    for (int mt = 0; mt < 2; mt++)
#pragma unroll
        for (int nt = 0; nt < 4; nt++)
#pragma unroll
            for (int i = 0; i < 4; i++) acc[mt][nt][i] = 0.f;

    for (int k0 = 0; k0 < K; k0 += 32) {
        // A tile 64x32 (coalesced global reads, conflict-free shared writes)
#pragma unroll
        for (int r = 0; r < 8; r++) {
            int idx = tid + r * 256;
            int mm = idx >> 5, kk = idx & 31;
            int gm = m0 + mm, gk = k0 + kk;
            float v = (gm < NR && gk < K) ? A[(size_t)gm * lda + gk] : 0.f;
            As[mm][kk] = f2tf32(v);
        }
        // B tile 32x128
#pragma unroll
        for (int r = 0; r < 16; r++) {
            int idx = tid + r * 256;
            int kk = idx >> 7, nn = idx & 127;
            int gk = k0 + kk, gn = n0 + nn;
            float v = (gk < K && gn < M) ? W[(size_t)gk * ldb + gn] : 0.f;
            Bs[kk][nn] = f2tf32(v);
        }
        __syncthreads();

#pragma unroll
        for (int ks = 0; ks < 4; ks++) {
            const int kb = ks * 8;
            unsigned a[2][4];
#pragma unroll
            for (int mt = 0; mt < 2; mt++) {
                int row = wm + mt * 16;
                a[mt][0] = As[row + g][kb + tg];
                a[mt][1] = As[row + g + 8][kb + tg];
                a[mt][2] = As[row + g][kb + tg + 4];
                a[mt][3] = As[row + g + 8][kb + tg + 4];
            }
            unsigned b[4][2];
#pragma unroll
            for (int nt = 0; nt < 4; nt++) {
                int col = wn + nt * 8;
                b[nt][0] = Bs[kb + tg][col + g];
                b[nt][1] = Bs[kb + tg + 4][col + g];
            }
#pragma unroll
            for (int mt = 0; mt < 2; mt++)
#pragma unroll
                for (int nt = 0; nt < 4; nt++)
                    mma_tf32(acc[mt][nt], a[mt], b[nt]);
        }
        __syncthreads();
    }

    // epilogue: c0=(g,2tg) c1=(g,2tg+1) c2=(g+8,2tg) c3=(g+8,2tg+1)
#pragma unroll
    for (int mt = 0; mt < 2; mt++) {
#pragma unroll
        for (int nt = 0; nt < 4; nt++) {
#pragma unroll
            for (int i = 0; i < 4; i++) {
                int row = m0 + wm + mt * 16 + g + ((i >= 2) ? 8 : 0);
                int col = n0 + wn + nt * 8 + 2 * tg + (i & 1);
                if (row >= NR || col >= M) continue;
                float v = acc[mt][nt][i] + bias[col];
                v = fmaxf(v, 0.f);
                if (EPI == 2) {
                    C[(size_t)row * ldc + col] = v * dinv[row];
                } else {  // 3: maxpool
                    atomicMax(&pool[(size_t)batch[row] * ldc + col], __float_as_uint(v));
                }
            }
        }
    }
}

// ---------------------------------------------------------------------------
// Scalar f32 SIMT GEMM (for the small head GEMMs): C[NR,M] = A[NR,K] @ W[K,M]
// Epilogues: 0 STORE, 1 RELU, 4 ADD_ATOMIC (split-K)
// ---------------------------------------------------------------------------
#define GBM 128
#define GBN 64
#define GBK 16

template <int EPI>
__global__ __launch_bounds__(256)
void k_gemm(const float* __restrict__ A, int lda,
            const float* __restrict__ W, int ldb,
            float* __restrict__ C, int ldc,
            int NR, int M, int K,
            const float* __restrict__ bias,
            int kChunk) {
    __shared__ float As[GBK][GBM + 4];
    __shared__ float Bs[GBK][GBN + 4];

    const int m0 = blockIdx.x * GBM;
    const int n0 = blockIdx.y * GBN;
    const int kb = blockIdx.z * kChunk;
    const int ke = min(K, kb + kChunk);

    const int tid = threadIdx.x;
    const int tN = tid & 15;   // 16 col groups
    const int tM = tid >> 4;   // 16 row groups

    float acc[8][4];
#pragma unroll
    for (int i = 0; i < 8; i++)
#pragma unroll
        for (int j = 0; j < 4; j++) acc[i][j] = 0.f;

    for (int k0 = kb; k0 < ke; k0 += GBK) {
#pragma unroll
        for (int r = 0; r < 8; r++) {
            int idx = tid + r * 256;
            int mm = idx >> 4, kk = idx & 15;
            int gm = m0 + mm, gk = k0 + kk;
            As[kk][mm] = (gm < NR && gk < ke) ? A[(size_t)gm * lda + gk] : 0.f;
        }
#pragma unroll
        for (int r = 0; r < 4; r++) {
            int idx = tid + r * 256;
            int kk = idx >> 6, nn = idx & 63;
            int gk = k0 + kk, gn = n0 + nn;
            Bs[kk][nn] = (gk < ke && gn < M) ? W[(size_t)gk * ldb + gn] : 0.f;
        }
        __syncthreads();
#pragma unroll
        for (int kk = 0; kk < GBK; kk++) {
            float4 a0 = *reinterpret_cast<const float4*>(&As[kk][tM * 8]);
            float4 a1 = *reinterpret_cast<const float4*>(&As[kk][tM * 8 + 4]);
            float4 b0 = *reinterpret_cast<const float4*>(&Bs[kk][tN * 4]);
            float a[8] = {a0.x, a0.y, a0.z, a0.w, a1.x, a1.y, a1.z, a1.w};
            float b[4] = {b0.x, b0.y, b0.z, b0.w};
#pragma unroll
            for (int i = 0; i < 8; i++)
#pragma unroll
                for (int j = 0; j < 4; j++)
                    acc[i][j] = fmaf(a[i], b[j], acc[i][j]);
        }
        __syncthreads();
    }

#pragma unroll
    for (int i = 0; i < 8; i++) {
        int row = m0 + tM * 8 + i;
        if (row >= NR) continue;
#pragma unroll
        for (int j = 0; j < 4; j++) {
            int col = n0 + tN * 4 + j;
            if (col >= M) continue;
            float v = acc[i][j];
            if (EPI == 0) {
                if (bias) v += bias[col];
                C[(size_t)row * ldc + col] = v;
            } else if (EPI == 1) {
                v += bias[col];
                C[(size_t)row * ldc + col] = fmaxf(v, 0.f);
            } else {  // 4
                if (blockIdx.z == 0 && bias) v += bias[col];
                atomicAdd(&C[(size_t)row * ldc + col], v);
            }
        }
    }
}

// ---------------------------------------------------------------------------
// Protein branch: G[b,o,k,l] = sum_i conv_w[o,i,k] * [target[b,i] == l]
// ---------------------------------------------------------------------------
__global__ void k_gbuild(const int* __restrict__ target, const float* __restrict__ conv_w) {
    __shared__ int   ts[1000];
    __shared__ float acc[256 * 26];
    const int b = blockIdx.x, tid = threadIdx.x;
    for (int i = tid; i < 1000; i += 256) ts[i] = target[b * 1000 + i];
#pragma unroll
    for (int l = 0; l < 26; l++) acc[tid * 26 + l] = 0.f;
    __syncthreads();
    const int o = tid >> 3, k = tid & 7;
    const float* wp = conv_w + o * 8000 + k;
    for (int i = 0; i < 1000; i++) {
        acc[tid * 26 + ts[i]] += wp[i * 8];
    }
    float* g = g_G + (size_t)b * 6656 + tid * 26;
#pragma unroll
    for (int l = 0; l < 26; l++) g[l] = acc[tid * 26 + l];
}

// c[b,o,h] = conv_b[o] + sum_{k,l} G[b,o,k,l] * emb[l, h+k]
__global__ void k_cconv(const float* __restrict__ emb, const float* __restrict__ conv_b) {
    __shared__ float Gs[6656];
    __shared__ float Es[26 * 128];
    const int b = blockIdx.x, tid = threadIdx.x;
    for (int i = tid; i < 6656; i += 256) Gs[i] = g_G[(size_t)b * 6656 + i];
    for (int i = tid; i < 26 * 128; i += 256) Es[i] = emb[i];
    __syncthreads();
    for (int idx = tid; idx < 3872; idx += 256) {
        int o = idx / 121, h = idx % 121;
        float s = conv_b[o];
#pragma unroll
        for (int k = 0; k < 8; k++)
#pragma unroll
            for (int l = 0; l < 26; l++)
                s += Gs[(o * 8 + k) * 26 + l] * Es[l * 128 + h + k];
        g_Cbuf[(size_t)b * 3872 + idx] = s;
    }
}

// ---------------------------------------------------------------------------
// Final projection: out[r] = dot(S2[r,:512], out_w) + out_b. One warp per row.
// ---------------------------------------------------------------------------
__global__ void k_out(const float* __restrict__ ow, const float* __restrict__ ob,
                      float* __restrict__ out, int rows) {
    int row = blockIdx.x * 8 + (threadIdx.x >> 5);
    int lane = threadIdx.x & 31;
    if (row >= rows) return;
    float s = 0.f;
    for (int j = lane; j < 512; j += 32) s += g_S2[row * 512 + j] * ow[j];
#pragma unroll
    for (int off = 16; off; off >>= 1) s += __shfl_down_sync(0xffffffffu, s, off);
    if (lane == 0) out[row] = s + ob[0];
}

// ---------------------------------------------------------------------------
// Launch
// ---------------------------------------------------------------------------
extern "C" void kernel_launch(void* const* d_in, const int* in_sizes, int n_in,
                              void* d_out, int out_size) {
    const float* x       = (const float*)d_in[0];
    const int*   ei      = (const int*)d_in[1];      // [2, E]: row0 src, row1 dst
    const int*   batch   = (const int*)d_in[2];
    const int*   target  = (const int*)d_in[3];
    const float* W1      = (const float*)d_in[4];
    const float* b1      = (const float*)d_in[5];
    const float* W2      = (const float*)d_in[6];
    const float* b2      = (const float*)d_in[7];
    const float* W3      = (const float*)d_in[8];
    const float* b3      = (const float*)d_in[9];
    const float* fcg1_w  = (const float*)d_in[10];
    const float* fcg1_b  = (const float*)d_in[11];
    const float* fcg2_w  = (const float*)d_in[12];
    const float* fcg2_b  = (const float*)d_in[13];
    const float* emb     = (const float*)d_in[14];
    const float* conv_w  = (const float*)d_in[15];
    const float* conv_b  = (const float*)d_in[16];
    const float* fcxt_w  = (const float*)d_in[17];
    const float* fcxt_b  = (const float*)d_in[18];
    const float* fc1_w   = (const float*)d_in[19];
    const float* fc1_b   = (const float*)d_in[20];
    const float* fc2_w   = (const float*)d_in[21];
    const float* fc2_b   = (const float*)d_in[22];
    const float* out_w   = (const float*)d_in[23];
    const float* out_b   = (const float*)d_in[24];
    float* out = (float*)d_out;

    float *bufA, *bufB, *dinv, *S1, *S2, *xc, *Cbuf;
    int *cnt;
    unsigned* pool;
    cudaGetSymbolAddress((void**)&bufA, g_bufA);
    cudaGetSymbolAddress((void**)&bufB, g_bufB);
    cudaGetSymbolAddress((void**)&dinv, g_dinv);
    cudaGetSymbolAddress((void**)&cnt,  g_cnt);
    cudaGetSymbolAddress((void**)&pool, g_pool);
    cudaGetSymbolAddress((void**)&S1,   g_S1);
    cudaGetSymbolAddress((void**)&S2,   g_S2);
    cudaGetSymbolAddress((void**)&xc,   g_xc);
    cudaGetSymbolAddress((void**)&Cbuf, g_Cbuf);

    const int N = NN, E = EE, B = BB;
    const int NB = (N + 511) / 512;               // 489 scan blocks
    const int MT = (N + 63) / 64;                 // 3907 tc row blocks

    // ---- CSR + dinv ----
    k_zero_int<<<(N + 255) / 256, 256>>>(cnt, N);
    k_count<<<(E + 255) / 256, 256>>>(ei + E, E);
    k_scan1<<<NB, 512>>>(N);
    k_scan2<<<1, 512>>>(NB);
    k_scan3<<<(N + 255) / 256, 256>>>(N, E);
    k_fill<<<(E + 255) / 256, 256>>>(ei, ei + E, E);

    // ---- GCN layers (aggregate-then-GEMM, TF32 tensor cores) ----
    k_agg<78, false><<<N / 8, 256>>>(x, bufA, N);
    k_tc<2><<<dim3(MT, 1), 256>>>(bufA, 78, W1, 78, bufB, 78, N, 78, 78,
                                  b1, dinv, nullptr, nullptr);
    k_agg<78, true><<<N / 8, 256>>>(bufB, bufA, N);
    k_tc<2><<<dim3(MT, 2), 256>>>(bufA, 78, W2, 156, bufB, 156, N, 156, 78,
                                  b2, dinv, nullptr, nullptr);
    k_agg<156, true><<<N / 8, 256>>>(bufB, bufA, N);
    k_zero_u32<<<(B * 312 + 255) / 256, 256>>>(pool, B * 312);
    k_tc<3><<<dim3(MT, 3), 256>>>(bufA, 156, W3, 312, nullptr, 312, N, 312, 156,
                                  b3, nullptr, batch, pool);

    // ---- graph head ----
    k_gemm<1><<<dim3(4, 16), 256>>>((const float*)pool, 312, fcg1_w, 1024, S1, 1024,
                                    B, 1024, 312, fcg1_b, 312);
    k_zero_f32<<<(B * 256 + 255) / 256, 256>>>(xc, B * 256);
    k_gemm<0><<<dim3(4, 2), 256>>>(S1, 1024, fcg2_w, 128, xc, 256,
                                   B, 128, 1024, fcg2_b, 1024);

    // ---- protein branch (alphabet-factored conv) ----
    k_gbuild<<<B, 256>>>(target, conv_w);
    k_cconv<<<B, 256>>>(emb, conv_b);
    k_gemm<4><<<dim3(4, 2, 16), 256>>>(Cbuf, 3872, fcxt_w, 128, xc + 128, 256,
                                       B, 128, 3872, fcxt_b, 242);

    // ---- fusion head ----
    k_gemm<1><<<dim3(4, 16), 256>>>(xc, 256, fc1_w, 1024, S1, 1024,
                                    B, 1024, 256, fc1_b, 256);
    k_gemm<1><<<dim3(4, 8), 256>>>(S1, 1024, fc2_w, 512, S2, 512,
                                   B, 512, 1024, fc2_b, 1024);
    k_out<<<(B + 7) / 8, 256>>>(out_w, out_b, out, B);
}

// round 5
// speedup vs baseline: 1.8454x; 1.6184x over previous
#include <cuda_runtime.h>
#include <cuda_fp16.h>
#include <cstdint>

// ---------------------------------------------------------------------------
// Problem constants (fixed by setup_inputs)
// ---------------------------------------------------------------------------
#define NN 250000
#define EE 1000000
#define BB 500
#define FD 78

// ---------------------------------------------------------------------------
// Scratch (device globals: no allocation allowed)
// ---------------------------------------------------------------------------
__device__ float    g_bufA[NN * 156];        // 156 MB
__device__ float    g_bufB[NN * 156];        // 156 MB
__device__ float    g_dinv[NN];
__device__ int      g_cnt[NN];
__device__ int      g_rowptr[NN + 1];
__device__ int      g_cursor[NN];
__device__ int      g_csrc[EE];
__device__ int      g_bsum[512];
__device__ int      g_boff[512];
__device__ unsigned g_pool[BB * 312];
__device__ float    g_S1[BB * 1024];
__device__ float    g_S2[BB * 512];
__device__ float    g_xc[BB * 256];
__device__ float    g_G[BB * 256 * 26];      // [b][o*8+k][l]
__device__ float    g_Cbuf[BB * 3872];

// ---------------------------------------------------------------------------
// mma / ldmatrix helpers (PTX ISA sm_80+, legal at compute_103)
// ---------------------------------------------------------------------------
__device__ __forceinline__ uint32_t smem_u32(const void* p) {
    uint32_t a;
    asm("{ .reg .u64 t; cvta.to.shared.u64 t, %1; cvt.u32.u64 %0, t; }" : "=r"(a) : "l"(p));
    return a;
}
__device__ __forceinline__ void ldm4(uint32_t* r, uint32_t addr) {
    asm volatile("ldmatrix.sync.aligned.m8n8.x4.shared.b16 {%0,%1,%2,%3}, [%4];"
        : "=r"(r[0]), "=r"(r[1]), "=r"(r[2]), "=r"(r[3]) : "r"(addr));
}
__device__ __forceinline__ void mma16816(float* c, const uint32_t* a, const uint32_t* b) {
    asm volatile(
        "mma.sync.aligned.m16n8k16.row.col.f32.f16.f16.f32 "
        "{%0,%1,%2,%3}, {%4,%5,%6,%7}, {%8,%9}, {%0,%1,%2,%3};"
        : "+f"(c[0]), "+f"(c[1]), "+f"(c[2]), "+f"(c[3])
        : "r"(a[0]), "r"(a[1]), "r"(a[2]), "r"(a[3]), "r"(b[0]), "r"(b[1]));
}

// ---------------------------------------------------------------------------
// Small utility kernels
// ---------------------------------------------------------------------------
__global__ void k_zero_int(int* p, int n) {
    int i = blockIdx.x * blockDim.x + threadIdx.x;
    if (i < n) p[i] = 0;
}
__global__ void k_zero_u32(unsigned* p, int n) {
    int i = blockIdx.x * blockDim.x + threadIdx.x;
    if (i < n) p[i] = 0u;
}
__global__ void k_zero_f32(float* p, int n) {
    int i = blockIdx.x * blockDim.x + threadIdx.x;
    if (i < n) p[i] = 0.f;
}

// ---------------------------------------------------------------------------
// CSR build: count -> scan -> offsets -> fill
// ---------------------------------------------------------------------------
__global__ void k_count(const int* __restrict__ dst, int e) {
    int i = blockIdx.x * blockDim.x + threadIdx.x;
    if (i < e) atomicAdd(&g_cnt[dst[i]], 1);
}

__global__ void k_scan1(int n) {
    __shared__ int s[512];
    int t = threadIdx.x;
    int i = blockIdx.x * 512 + t;
    int v = (i < n) ? g_cnt[i] : 0;
    s[t] = v;
    __syncthreads();
    for (int off = 1; off < 512; off <<= 1) {
        int tmp = (t >= off) ? s[t - off] : 0;
        __syncthreads();
        s[t] += tmp;
        __syncthreads();
    }
    if (i < n) g_rowptr[i] = s[t] - v;
    if (t == 511) g_bsum[blockIdx.x] = s[511];
}

__global__ void k_scan2(int nb) {
    __shared__ int s[512];
    int t = threadIdx.x;
    int v = (t < nb) ? g_bsum[t] : 0;
    s[t] = v;
    __syncthreads();
    for (int off = 1; off < 512; off <<= 1) {
        int tmp = (t >= off) ? s[t - off] : 0;
        __syncthreads();
        s[t] += tmp;
        __syncthreads();
    }
    if (t < nb) g_boff[t] = s[t] - v;
}

__global__ void k_scan3(int n, int e) {
    int i = blockIdx.x * blockDim.x + threadIdx.x;
    if (i < n) {
        int v = g_rowptr[i] + g_boff[i >> 9];
        g_rowptr[i] = v;
        g_cursor[i] = v;
        g_dinv[i] = rsqrtf((float)g_cnt[i] + 1.0f);
    }
    if (i == 0) g_rowptr[n] = e;
}

__global__ void k_fill(const int* __restrict__ src, const int* __restrict__ dst, int e) {
    int i = blockIdx.x * blockDim.x + threadIdx.x;
    if (i < e) {
        int d = dst[i];
        int p = atomicAdd(&g_cursor[d], 1);
        g_csrc[p] = src[i];
    }
}

// ---------------------------------------------------------------------------
// Aggregation: out[v] = dinv[v] * ( s(v)*in[v] + sum_{u in N(v)} s(u)*in[u] )
// ---------------------------------------------------------------------------
template <int F, bool PRESCALED>
__global__ void k_agg(const float* __restrict__ in, float* __restrict__ out, int n) {
    int warp = (blockIdx.x * blockDim.x + threadIdx.x) >> 5;
    int lane = threadIdx.x & 31;
    if (warp >= n) return;
    const int v = warp;
    constexpr int R = (F + 31) / 32;
    float dv = g_dinv[v];
    float ss = PRESCALED ? 1.f : dv;
    float acc[R];
#pragma unroll
    for (int i = 0; i < R; i++) {
        int f = lane + 32 * i;
        acc[i] = (f < F) ? in[(size_t)v * F + f] * ss : 0.f;
    }
    int e0 = g_rowptr[v], e1 = g_rowptr[v + 1];
    for (int e = e0; e < e1; e++) {
        int u = g_csrc[e];
        float us = PRESCALED ? 1.f : g_dinv[u];
#pragma unroll
        for (int i = 0; i < R; i++) {
            int f = lane + 32 * i;
            if (f < F) acc[i] += in[(size_t)u * F + f] * us;
        }
    }
#pragma unroll
    for (int i = 0; i < R; i++) {
        int f = lane + 32 * i;
        if (f < F) out[(size_t)v * F + f] = acc[i] * dv;
    }
}

// ---------------------------------------------------------------------------
// fp16 HMMA GEMM: C[node, feat] = X[node, Kin] @ W[Kin, Mout], fp32 accum.
// Block tile 128(M=nodes) x 64(N=feats), whole K in smem (KTILE = padded K).
// 8 warps: 4 along M x 2 along N; warp tile 32x32 = 2(mt) x 4(nt) m16n8k16.
// Smem: A[128][KTILE] halfs pitch PA=KTILE+8 (conflict-free ldmatrix),
//       B=W^T tile [64][KTILE] halfs pitch PB=KTILE+8.
// EPI 2: C = relu(acc + bias) * dinv[node]   (fp32 store, float2)
// EPI 3: maxpool: atomicMax(pool[batch*312+feat], relu(max4(acc)+bias))
// ---------------------------------------------------------------------------
template <int KTILE, int EPI>
__global__ __launch_bounds__(256)
void k_hmma(const float* __restrict__ X, int lda, int Kin,
            const float* __restrict__ W, int Mout,
            float* __restrict__ C, int ldc,
            int NR,
            const float* __restrict__ bias,
            const int* __restrict__ batch,
            unsigned* __restrict__ pool) {
    constexpr int PA = KTILE + 8;
    constexpr int KS = KTILE / 16;
    extern __shared__ __half sm[];
    __half* Asm = sm;                       // [128][PA]
    __half* Bsm = sm + 128 * PA;            // [64][PA]

    const int tid = threadIdx.x;
    const int wid = tid >> 5;
    const int lane = tid & 31;
    const int m0 = blockIdx.x * 128;        // node base
    const int n0 = blockIdx.y * 64;         // feat base
    const int wm = (wid & 3) * 32;          // warp node offset
    const int wn = (wid >> 2) * 32;         // warp feat offset
    const int g = lane >> 2, tg = lane & 3; // frag ownership
    const int r8 = lane & 7, q = lane >> 3; // ldmatrix addressing

    // ---- fill A: X[node][k] -> fp16, zero-pad ----
#pragma unroll 4
    for (int idx = tid; idx < 128 * (KTILE / 2); idx += 256) {
        int row = idx / (KTILE / 2);
        int k = (idx - row * (KTILE / 2)) * 2;
        int node = m0 + row;
        float2 v = make_float2(0.f, 0.f);
        if (node < NR && k < Kin) v = *(const float2*)&X[(size_t)node * lda + k];
        *(__half2*)&Asm[row * PA + k] = __floats2half2_rn(v.x, v.y);
    }
    // ---- fill B: W^T[n][k] -> fp16 (transposed read, coalesced over n) ----
#pragma unroll 4
    for (int idx = tid; idx < 64 * (KTILE / 2); idx += 256) {
        int k2 = idx >> 6;
        int n = idx & 63;
        int k = k2 * 2;
        int feat = n0 + n;
        float v0 = 0.f, v1 = 0.f;
        if (feat < Mout && k < Kin) {
            v0 = W[(size_t)k * Mout + feat];
            v1 = W[(size_t)(k + 1) * Mout + feat];
        }
        *(__half2*)&Bsm[n * PA + k] = __floats2half2_rn(v0, v1);
    }
    __syncthreads();

    const uint32_t sA = smem_u32(Asm);
    const uint32_t sB = smem_u32(Bsm);

    // ldmatrix base addresses (per lane), advanced by 32B per ks
    uint32_t aAddr[2], bAddr[2];
#pragma unroll
    for (int mt = 0; mt < 2; mt++)
        aAddr[mt] = sA + (uint32_t)((wm + mt * 16 + r8 + (q & 1) * 8) * PA + (q >> 1) * 8) * 2;
#pragma unroll
    for (int h = 0; h < 2; h++)
        bAddr[h] = sB + (uint32_t)((wn + h * 16 + r8 + (q >> 1) * 8) * PA + (q & 1) * 8) * 2;

    float acc[2][4][4];
#pragma unroll
    for (int mt = 0; mt < 2; mt++)
#pragma unroll
        for (int nt = 0; nt < 4; nt++)
#pragma unroll
            for (int i = 0; i < 4; i++) acc[mt][nt][i] = 0.f;

#pragma unroll
    for (int ks = 0; ks < KS; ks++) {
        uint32_t a[2][4], b[2][4];
        ldm4(a[0], aAddr[0] + ks * 32u);
        ldm4(a[1], aAddr[1] + ks * 32u);
        ldm4(b[0], bAddr[0] + ks * 32u);
        ldm4(b[1], bAddr[1] + ks * 32u);
#pragma unroll
        for (int mt = 0; mt < 2; mt++)
#pragma unroll
            for (int nt = 0; nt < 4; nt++)
                mma16816(acc[mt][nt], a[mt], &b[nt >> 1][(nt & 1) * 2]);
    }

    // ---- epilogue ----
    if (EPI == 2) {
#pragma unroll
        for (int mt = 0; mt < 2; mt++) {
#pragma unroll
            for (int h = 0; h < 2; h++) {
                int node = m0 + wm + mt * 16 + g + h * 8;
                if (node >= NR) continue;
                float dv = g_dinv[node];
#pragma unroll
                for (int nt = 0; nt < 4; nt++) {
                    int feat = n0 + wn + nt * 8 + 2 * tg;
                    if (feat >= Mout) continue;
                    float2 o;
                    o.x = fmaxf(acc[mt][nt][h * 2 + 0] + bias[feat], 0.f) * dv;
                    o.y = fmaxf(acc[mt][nt][h * 2 + 1] + bias[feat + 1], 0.f) * dv;
                    *(float2*)&C[(size_t)node * ldc + feat] = o;
                }
            }
        }
    } else {  // EPI 3: maxpool over nodes (batch ids sorted)
        int nodeA = m0 + wm + g;            // +0,+8,+16,+24 variants
        bool allv = (nodeA + 24) < NR;
        bool samegraph = allv && (batch[nodeA] == batch[nodeA + 24]);
        if (samegraph) {
            int bg = batch[nodeA];
#pragma unroll
            for (int nt = 0; nt < 4; nt++) {
                int feat = n0 + wn + nt * 8 + 2 * tg;
                if (feat >= Mout) continue;
#pragma unroll
                for (int e = 0; e < 2; e++) {
                    float m = fmaxf(fmaxf(acc[0][nt][e], acc[0][nt][2 + e]),
                                    fmaxf(acc[1][nt][e], acc[1][nt][2 + e]));
                    float v = fmaxf(m + bias[feat + e], 0.f);
                    if (v > 0.f)
                        atomicMax(&pool[(size_t)bg * 312 + feat + e], __float_as_uint(v));
                }
            }
        } else {
#pragma unroll
            for (int mt = 0; mt < 2; mt++) {
#pragma unroll
                for (int h = 0; h < 2; h++) {
                    int node = m0 + wm + mt * 16 + g + h * 8;
                    if (node >= NR) continue;
                    int bg = batch[node];
#pragma unroll
                    for (int nt = 0; nt < 4; nt++) {
                        int feat = n0 + wn + nt * 8 + 2 * tg;
                        if (feat >= Mout) continue;
#pragma unroll
                        for (int e = 0; e < 2; e++) {
                            float v = fmaxf(acc[mt][nt][h * 2 + e] + bias[feat + e], 0.f);
                            if (v > 0.f)
                                atomicMax(&pool[(size_t)bg * 312 + feat + e], __float_as_uint(v));
                        }
                    }
                }
            }
        }
    }
}

// ---------------------------------------------------------------------------
// Scalar f32 SIMT GEMM (small head GEMMs): C[NR,M] = A[NR,K] @ W[K,M]
// Epilogues: 0 STORE, 1 RELU, 4 ADD_ATOMIC (split-K)
// ---------------------------------------------------------------------------
#define GBM 128
#define GBN 64
#define GBK 16

template <int EPI>
__global__ __launch_bounds__(256)
void k_gemm(const float* __restrict__ A, int lda,
            const float* __restrict__ W, int ldb,
            float* __restrict__ C, int ldc,
            int NR, int M, int K,
            const float* __restrict__ bias,
            int kChunk) {
    __shared__ float As[GBK][GBM + 4];
    __shared__ float Bs[GBK][GBN + 4];

    const int m0 = blockIdx.x * GBM;
    const int n0 = blockIdx.y * GBN;
    const int kb = blockIdx.z * kChunk;
    const int ke = min(K, kb + kChunk);

    const int tid = threadIdx.x;
    const int tN = tid & 15;
    const int tM = tid >> 4;

    float acc[8][4];
#pragma unroll
    for (int i = 0; i < 8; i++)
#pragma unroll
        for (int j = 0; j < 4; j++) acc[i][j] = 0.f;

    for (int k0 = kb; k0 < ke; k0 += GBK) {
#pragma unroll
        for (int r = 0; r < 8; r++) {
            int idx = tid + r * 256;
            int mm = idx >> 4, kk = idx & 15;
            int gm = m0 + mm, gk = k0 + kk;
            As[kk][mm] = (gm < NR && gk < ke) ? A[(size_t)gm * lda + gk] : 0.f;
        }
#pragma unroll
        for (int r = 0; r < 4; r++) {
            int idx = tid + r * 256;
            int kk = idx >> 6, nn = idx & 63;
            int gk = k0 + kk, gn = n0 + nn;
            Bs[kk][nn] = (gk < ke && gn < M) ? W[(size_t)gk * ldb + gn] : 0.f;
        }
        __syncthreads();
#pragma unroll
        for (int kk = 0; kk < GBK; kk++) {
            float4 a0 = *reinterpret_cast<const float4*>(&As[kk][tM * 8]);
            float4 a1 = *reinterpret_cast<const float4*>(&As[kk][tM * 8 + 4]);
            float4 b0 = *reinterpret_cast<const float4*>(&Bs[kk][tN * 4]);
            float a[8] = {a0.x, a0.y, a0.z, a0.w, a1.x, a1.y, a1.z, a1.w};
            float b[4] = {b0.x, b0.y, b0.z, b0.w};
#pragma unroll
            for (int i = 0; i < 8; i++)
#pragma unroll
                for (int j = 0; j < 4; j++)
                    acc[i][j] = fmaf(a[i], b[j], acc[i][j]);
        }
        __syncthreads();
    }

#pragma unroll
    for (int i = 0; i < 8; i++) {
        int row = m0 + tM * 8 + i;
        if (row >= NR) continue;
#pragma unroll
        for (int j = 0; j < 4; j++) {
            int col = n0 + tN * 4 + j;
            if (col >= M) continue;
            float v = acc[i][j];
            if (EPI == 0) {
                if (bias) v += bias[col];
                C[(size_t)row * ldc + col] = v;
            } else if (EPI == 1) {
                v += bias[col];
                C[(size_t)row * ldc + col] = fmaxf(v, 0.f);
            } else {  // 4
                if (blockIdx.z == 0 && bias) v += bias[col];
                atomicAdd(&C[(size_t)row * ldc + col], v);
            }
        }
    }
}

// ---------------------------------------------------------------------------
// Protein branch: G[b,o,k,l] = sum_i conv_w[o,i,k] * [target[b,i] == l]
// ---------------------------------------------------------------------------
__global__ void k_gbuild(const int* __restrict__ target, const float* __restrict__ conv_w) {
    __shared__ int   ts[1000];
    __shared__ float acc[256 * 26];
    const int b = blockIdx.x, tid = threadIdx.x;
    for (int i = tid; i < 1000; i += 256) ts[i] = target[b * 1000 + i];
#pragma unroll
    for (int l = 0; l < 26; l++) acc[tid * 26 + l] = 0.f;
    __syncthreads();
    const int o = tid >> 3, k = tid & 7;
    const float* wp = conv_w + o * 8000 + k;
    for (int i = 0; i < 1000; i++) {
        acc[tid * 26 + ts[i]] += wp[i * 8];
    }
    float* g = g_G + (size_t)b * 6656 + tid * 26;
#pragma unroll
    for (int l = 0; l < 26; l++) g[l] = acc[tid * 26 + l];
}

// c[b,o,h] = conv_b[o] + sum_{k,l} G[b,o,k,l] * emb[l, h+k]
__global__ void k_cconv(const float* __restrict__ emb, const float* __restrict__ conv_b) {
    __shared__ float Gs[6656];
    __shared__ float Es[26 * 128];
    const int b = blockIdx.x, tid = threadIdx.x;
    for (int i = tid; i < 6656; i += 256) Gs[i] = g_G[(size_t)b * 6656 + i];
    for (int i = tid; i < 26 * 128; i += 256) Es[i] = emb[i];
    __syncthreads();
    for (int idx = tid; idx < 3872; idx += 256) {
        int o = idx / 121, h = idx % 121;
        float s = conv_b[o];
#pragma unroll
        for (int k = 0; k < 8; k++)
#pragma unroll
            for (int l = 0; l < 26; l++)
                s += Gs[(o * 8 + k) * 26 + l] * Es[l * 128 + h + k];
        g_Cbuf[(size_t)b * 3872 + idx] = s;
    }
}

// ---------------------------------------------------------------------------
// Final projection
// ---------------------------------------------------------------------------
__global__ void k_out(const float* __restrict__ ow, const float* __restrict__ ob,
                      float* __restrict__ out, int rows) {
    int row = blockIdx.x * 8 + (threadIdx.x >> 5);
    int lane = threadIdx.x & 31;
    if (row >= rows) return;
    float s = 0.f;
    for (int j = lane; j < 512; j += 32) s += g_S2[row * 512 + j] * ow[j];
#pragma unroll
    for (int off = 16; off; off >>= 1) s += __shfl_down_sync(0xffffffffu, s, off);
    if (lane == 0) out[row] = s + ob[0];
}

// ---------------------------------------------------------------------------
// Launch
// ---------------------------------------------------------------------------
extern "C" void kernel_launch(void* const* d_in, const int* in_sizes, int n_in,
                              void* d_out, int out_size) {
    const float* x       = (const float*)d_in[0];
    const int*   ei      = (const int*)d_in[1];
    const int*   batch   = (const int*)d_in[2];
    const int*   target  = (const int*)d_in[3];
    const float* W1      = (const float*)d_in[4];
    const float* b1      = (const float*)d_in[5];
    const float* W2      = (const float*)d_in[6];
    const float* b2      = (const float*)d_in[7];
    const float* W3      = (const float*)d_in[8];
    const float* b3      = (const float*)d_in[9];
    const float* fcg1_w  = (const float*)d_in[10];
    const float* fcg1_b  = (const float*)d_in[11];
    const float* fcg2_w  = (const float*)d_in[12];
    const float* fcg2_b  = (const float*)d_in[13];
    const float* emb     = (const float*)d_in[14];
    const float* conv_w  = (const float*)d_in[15];
    const float* conv_b  = (const float*)d_in[16];
    const float* fcxt_w  = (const float*)d_in[17];
    const float* fcxt_b  = (const float*)d_in[18];
    const float* fc1_w   = (const float*)d_in[19];
    const float* fc1_b   = (const float*)d_in[20];
    const float* fc2_w   = (const float*)d_in[21];
    const float* fc2_b   = (const float*)d_in[22];
    const float* out_w   = (const float*)d_in[23];
    const float* out_b   = (const float*)d_in[24];
    float* out = (float*)d_out;

    float *bufA, *bufB, *S1, *S2, *xc, *Cbuf;
    int *cnt;
    unsigned* pool;
    cudaGetSymbolAddress((void**)&bufA, g_bufA);
    cudaGetSymbolAddress((void**)&bufB, g_bufB);
    cudaGetSymbolAddress((void**)&cnt,  g_cnt);
    cudaGetSymbolAddress((void**)&pool, g_pool);
    cudaGetSymbolAddress((void**)&S1,   g_S1);
    cudaGetSymbolAddress((void**)&S2,   g_S2);
    cudaGetSymbolAddress((void**)&xc,   g_xc);
    cudaGetSymbolAddress((void**)&Cbuf, g_Cbuf);

    const int N = NN, E = EE, B = BB;
    const int NB = (N + 511) / 512;
    const int MH = (N + 127) / 128;               // 1954 hmma row blocks

    // smem sizes: (128+64) rows * (KTILE+8) halfs * 2B
    const int SM12 = 192 * (80 + 8) * 2;          // 33792
    const int SM3  = 192 * (160 + 8) * 2;         // 64512
    cudaFuncSetAttribute(k_hmma<80, 2>,  cudaFuncAttributeMaxDynamicSharedMemorySize, SM12);
    cudaFuncSetAttribute(k_hmma<160, 3>, cudaFuncAttributeMaxDynamicSharedMemorySize, SM3);

    // ---- CSR + dinv ----
    k_zero_int<<<(N + 255) / 256, 256>>>(cnt, N);
    k_count<<<(E + 255) / 256, 256>>>(ei + E, E);
    k_scan1<<<NB, 512>>>(N);
    k_scan2<<<1, 512>>>(NB);
    k_scan3<<<(N + 255) / 256, 256>>>(N, E);
    k_fill<<<(E + 255) / 256, 256>>>(ei, ei + E, E);

    // ---- GCN layers: aggregate (fp32) then fp16-HMMA GEMM ----
    k_agg<78, false><<<N / 8, 256>>>(x, bufA, N);
    k_hmma<80, 2><<<dim3(MH, 2), 256, SM12>>>(bufA, 78, 78, W1, 78, bufB, 78, N,
                                              b1, nullptr, nullptr);
    k_agg<78, true><<<N / 8, 256>>>(bufB, bufA, N);
    k_hmma<80, 2><<<dim3(MH, 3), 256, SM12>>>(bufA, 78, 78, W2, 156, bufB, 156, N,
                                              b2, nullptr, nullptr);
    k_agg<156, true><<<N / 8, 256>>>(bufB, bufA, N);
    k_zero_u32<<<(B * 312 + 255) / 256, 256>>>(pool, B * 312);
    k_hmma<160, 3><<<dim3(MH, 5), 256, SM3>>>(bufA, 156, 156, W3, 312, nullptr, 312, N,
                                              b3, batch, pool);

    // ---- graph head ----
    k_gemm<1><<<dim3(4, 16), 256>>>((const float*)pool, 312, fcg1_w, 1024, S1, 1024,
                                    B, 1024, 312, fcg1_b, 312);
    k_zero_f32<<<(B * 256 + 255) / 256, 256>>>(xc, B * 256);
    k_gemm<0><<<dim3(4, 2), 256>>>(S1, 1024, fcg2_w, 128, xc, 256,
                                   B, 128, 1024, fcg2_b, 1024);

    // ---- protein branch (alphabet-factored conv) ----
    k_gbuild<<<B, 256>>>(target, conv_w);
    k_cconv<<<B, 256>>>(emb, conv_b);
    k_gemm<4><<<dim3(4, 2, 16), 256>>>(Cbuf, 3872, fcxt_w, 128, xc + 128, 256,
                                       B, 128, 3872, fcxt_b, 242);

    // ---- fusion head ----
    k_gemm<1><<<dim3(4, 16), 256>>>(xc, 256, fc1_w, 1024, S1, 1024,
                                    B, 1024, 256, fc1_b, 256);
    k_gemm<1><<<dim3(4, 8), 256>>>(S1, 1024, fc2_w, 512, S2, 512,
                                   B, 512, 1024, fc2_b, 1024);
    k_out<<<(B + 7) / 8, 256>>>(out_w, out_b, out, B);
}

// round 6
// speedup vs baseline: 2.1975x; 1.1908x over previous
#include <cuda_runtime.h>
#include <cuda_fp16.h>
#include <cstdint>

// ---------------------------------------------------------------------------
// Problem constants (fixed by setup_inputs)
// ---------------------------------------------------------------------------
#define NN 250000
#define EE 1000000
#define BB 500
#define FD 78

// ---------------------------------------------------------------------------
// Scratch (device globals: no allocation allowed)
// ---------------------------------------------------------------------------
__device__ float    g_bufA[NN * 156];        // reused as fp16 (pitch 80/160)
__device__ float    g_bufB[NN * 156];
__device__ float    g_dinv[NN];
__device__ int      g_cnt[NN];
__device__ int      g_rowptr[NN + 1];
__device__ int      g_cursor[NN];
__device__ int      g_csrc[EE];
__device__ int      g_bsum[512];
__device__ int      g_boff[512];
__device__ unsigned g_pool[BB * 312];
__device__ float    g_S1[BB * 1024];
__device__ float    g_S2[BB * 512];
__device__ float    g_xc[BB * 256];
__device__ float    g_G[BB * 256 * 26];      // [b][o*8+k][l]
__device__ float    g_Cbuf[BB * 3872];

// ---------------------------------------------------------------------------
// mma / ldmatrix helpers (PTX ISA sm_80+, legal at compute_103)
// ---------------------------------------------------------------------------
__device__ __forceinline__ uint32_t smem_u32(const void* p) {
    uint32_t a;
    asm("{ .reg .u64 t; cvta.to.shared.u64 t, %1; cvt.u32.u64 %0, t; }" : "=r"(a) : "l"(p));
    return a;
}
__device__ __forceinline__ void ldm4(uint32_t* r, uint32_t addr) {
    asm volatile("ldmatrix.sync.aligned.m8n8.x4.shared.b16 {%0,%1,%2,%3}, [%4];"
        : "=r"(r[0]), "=r"(r[1]), "=r"(r[2]), "=r"(r[3]) : "r"(addr));
}
__device__ __forceinline__ void mma16816(float* c, const uint32_t* a, const uint32_t* b) {
    asm volatile(
        "mma.sync.aligned.m16n8k16.row.col.f32.f16.f16.f32 "
        "{%0,%1,%2,%3}, {%4,%5,%6,%7}, {%8,%9}, {%0,%1,%2,%3};"
        : "+f"(c[0]), "+f"(c[1]), "+f"(c[2]), "+f"(c[3])
        : "r"(a[0]), "r"(a[1]), "r"(a[2]), "r"(a[3]), "r"(b[0]), "r"(b[1]));
}

// ---------------------------------------------------------------------------
// Small utility kernels
// ---------------------------------------------------------------------------
__global__ void k_zero_int(int* p, int n) {
    int i = blockIdx.x * blockDim.x + threadIdx.x;
    if (i < n) p[i] = 0;
}
__global__ void k_zero_u32(unsigned* p, int n) {
    int i = blockIdx.x * blockDim.x + threadIdx.x;
    if (i < n) p[i] = 0u;
}
__global__ void k_zero_f32(float* p, int n) {
    int i = blockIdx.x * blockDim.x + threadIdx.x;
    if (i < n) p[i] = 0.f;
}

// ---------------------------------------------------------------------------
// CSR build: count -> scan -> offsets -> fill
// ---------------------------------------------------------------------------
__global__ void k_count(const int* __restrict__ dst, int e) {
    int i = blockIdx.x * blockDim.x + threadIdx.x;
    if (i < e) atomicAdd(&g_cnt[dst[i]], 1);
}

__global__ void k_scan1(int n) {
    __shared__ int s[512];
    int t = threadIdx.x;
    int i = blockIdx.x * 512 + t;
    int v = (i < n) ? g_cnt[i] : 0;
    s[t] = v;
    __syncthreads();
    for (int off = 1; off < 512; off <<= 1) {
        int tmp = (t >= off) ? s[t - off] : 0;
        __syncthreads();
        s[t] += tmp;
        __syncthreads();
    }
    if (i < n) g_rowptr[i] = s[t] - v;
    if (t == 511) g_bsum[blockIdx.x] = s[511];
}

__global__ void k_scan2(int nb) {
    __shared__ int s[512];
    int t = threadIdx.x;
    int v = (t < nb) ? g_bsum[t] : 0;
    s[t] = v;
    __syncthreads();
    for (int off = 1; off < 512; off <<= 1) {
        int tmp = (t >= off) ? s[t - off] : 0;
        __syncthreads();
        s[t] += tmp;
        __syncthreads();
    }
    if (t < nb) g_boff[t] = s[t] - v;
}

__global__ void k_scan3(int n, int e) {
    int i = blockIdx.x * blockDim.x + threadIdx.x;
    if (i < n) {
        int v = g_rowptr[i] + g_boff[i >> 9];
        g_rowptr[i] = v;
        g_cursor[i] = v;
        g_dinv[i] = rsqrtf((float)g_cnt[i] + 1.0f);
    }
    if (i == 0) g_rowptr[n] = e;
}

__global__ void k_fill(const int* __restrict__ src, const int* __restrict__ dst, int e) {
    int i = blockIdx.x * blockDim.x + threadIdx.x;
    if (i < e) {
        int d = dst[i];
        int p = atomicAdd(&g_cursor[d], 1);
        g_csrc[p] = src[i];
    }
}

// ---------------------------------------------------------------------------
// Aggregation kernels (one warp per node).
// k_agg0: fp32 input x (lda floats), fp16 output (pitch P2 half2, pads zeroed)
//   out[v] = dv*( dv*x[v] + sum du*x[u] )
// k_agg_h: fp16 prescaled input -> fp16 output
//   out[v] = dv*( in[v] + sum in[u] )
// ---------------------------------------------------------------------------
template <int F2, int P2>
__global__ void k_agg0(const float* __restrict__ in, __half2* __restrict__ out,
                       int n, int ldin) {
    int warp = (blockIdx.x * blockDim.x + threadIdx.x) >> 5;
    int lane = threadIdx.x & 31;
    if (warp >= n) return;
    const int v = warp;
    constexpr int R = (F2 + 31) / 32;
    float dv = g_dinv[v];
    float2 acc[R];
#pragma unroll
    for (int i = 0; i < R; i++) {
        int f2 = lane + 32 * i;
        if (f2 < F2) {
            acc[i].x = in[(size_t)v * ldin + 2 * f2] * dv;
            acc[i].y = in[(size_t)v * ldin + 2 * f2 + 1] * dv;
        } else acc[i] = make_float2(0.f, 0.f);
    }
    int e0 = g_rowptr[v], e1 = g_rowptr[v + 1];
    for (int e = e0; e < e1; e++) {
        int u = g_csrc[e];
        float us = g_dinv[u];
#pragma unroll
        for (int i = 0; i < R; i++) {
            int f2 = lane + 32 * i;
            if (f2 < F2) {
                acc[i].x += in[(size_t)u * ldin + 2 * f2] * us;
                acc[i].y += in[(size_t)u * ldin + 2 * f2 + 1] * us;
            }
        }
    }
#pragma unroll
    for (int i = 0; i < R; i++) {
        int f2 = lane + 32 * i;
        if (f2 < F2)
            out[(size_t)v * P2 + f2] = __floats2half2_rn(acc[i].x * dv, acc[i].y * dv);
        else if (f2 < P2)
            out[(size_t)v * P2 + f2] = __floats2half2_rn(0.f, 0.f);
    }
}

template <int F2, int P2>
__global__ void k_agg_h(const __half2* __restrict__ in, __half2* __restrict__ out, int n) {
    int warp = (blockIdx.x * blockDim.x + threadIdx.x) >> 5;
    int lane = threadIdx.x & 31;
    if (warp >= n) return;
    const int v = warp;
    constexpr int R = (F2 + 31) / 32;
    float dv = g_dinv[v];
    float2 acc[R];
#pragma unroll
    for (int i = 0; i < R; i++) {
        int f2 = lane + 32 * i;
        acc[i] = (f2 < F2) ? __half22float2(in[(size_t)v * P2 + f2]) : make_float2(0.f, 0.f);
    }
    int e0 = g_rowptr[v], e1 = g_rowptr[v + 1];
    for (int e = e0; e < e1; e++) {
        int u = g_csrc[e];
#pragma unroll
        for (int i = 0; i < R; i++) {
            int f2 = lane + 32 * i;
            if (f2 < F2) {
                float2 t = __half22float2(in[(size_t)u * P2 + f2]);
                acc[i].x += t.x;
                acc[i].y += t.y;
            }
        }
    }
#pragma unroll
    for (int i = 0; i < R; i++) {
        int f2 = lane + 32 * i;
        if (f2 < F2)
            out[(size_t)v * P2 + f2] = __floats2half2_rn(acc[i].x * dv, acc[i].y * dv);
        else if (f2 < P2)
            out[(size_t)v * P2 + f2] = __floats2half2_rn(0.f, 0.f);
    }
}

// ---------------------------------------------------------------------------
// fp16 HMMA GEMM: C[node, feat] = X[node, Kin] @ W[Kin, Mout], fp32 accum.
// X is fp16, pitch lda == KTILE halfs (pads zeroed by producer).
// Block tile 128(nodes) x 64(feats), whole K in smem.
// Grid: (feat_tiles, node_tiles) -- feat fastest => A tile reused via L2.
// EPI 2: C[node*ldc+feat] = half( relu(acc + bias) * dinv[node] )
// EPI 3: maxpool: atomicMax(pool[batch*312+feat], relu(acc)+bias)
// ---------------------------------------------------------------------------
template <int KTILE, int EPI>
__global__ __launch_bounds__(256)
void k_hmma(const __half* __restrict__ X, int Kin,
            const float* __restrict__ W, int Mout,
            __half* __restrict__ C, int ldc,
            int NR,
            const float* __restrict__ bias,
            const int* __restrict__ batch,
            unsigned* __restrict__ pool) {
    constexpr int PA = KTILE + 8;
    constexpr int KS = KTILE / 16;
    constexpr int CW = KTILE / 8;           // uint4 chunks per A row
    extern __shared__ __half sm[];
    __half* Asm = sm;                       // [128][PA]
    __half* Bsm = sm + 128 * PA;            // [64][PA]

    const int tid = threadIdx.x;
    const int wid = tid >> 5;
    const int lane = tid & 31;
    const int n0 = blockIdx.x * 64;         // feat base   (fast dim)
    const int m0 = blockIdx.y * 128;        // node base
    const int wm = (wid & 3) * 32;
    const int wn = (wid >> 2) * 32;
    const int g = lane >> 2, tg = lane & 3;
    const int r8 = lane & 7, q = lane >> 3;

    // ---- fill A: raw fp16 copy (pads already zero) ----
#pragma unroll 4
    for (int idx = tid; idx < 128 * CW; idx += 256) {
        int row = idx / CW;
        int c = idx - row * CW;
        int node = m0 + row;
        uint4 v = make_uint4(0u, 0u, 0u, 0u);
        if (node < NR) v = *(const uint4*)&X[(size_t)node * KTILE + c * 8];
        *(uint4*)&Asm[row * PA + c * 8] = v;
    }
    // ---- fill B: W^T[n][k] -> fp16 (transposed read, coalesced over n) ----
#pragma unroll 4
    for (int idx = tid; idx < 64 * (KTILE / 2); idx += 256) {
        int k2 = idx >> 6;
        int n = idx & 63;
        int k = k2 * 2;
        int feat = n0 + n;
        float v0 = 0.f, v1 = 0.f;
        if (feat < Mout && k < Kin) {
            v0 = W[(size_t)k * Mout + feat];
            v1 = W[(size_t)(k + 1) * Mout + feat];
        }
        *(__half2*)&Bsm[n * PA + k] = __floats2half2_rn(v0, v1);
    }
    __syncthreads();

    const uint32_t sA = smem_u32(Asm);
    const uint32_t sB = smem_u32(Bsm);

    uint32_t aAddr[2], bAddr[2];
#pragma unroll
    for (int mt = 0; mt < 2; mt++)
        aAddr[mt] = sA + (uint32_t)((wm + mt * 16 + r8 + (q & 1) * 8) * PA + (q >> 1) * 8) * 2;
#pragma unroll
    for (int h = 0; h < 2; h++)
        bAddr[h] = sB + (uint32_t)((wn + h * 16 + r8 + (q >> 1) * 8) * PA + (q & 1) * 8) * 2;

    float acc[2][4][4];
#pragma unroll
    for (int mt = 0; mt < 2; mt++)
#pragma unroll
        for (int nt = 0; nt < 4; nt++)
#pragma unroll
            for (int i = 0; i < 4; i++) acc[mt][nt][i] = 0.f;

#pragma unroll
    for (int ks = 0; ks < KS; ks++) {
        uint32_t a[2][4], b[2][4];
        ldm4(a[0], aAddr[0] + ks * 32u);
        ldm4(a[1], aAddr[1] + ks * 32u);
        ldm4(b[0], bAddr[0] + ks * 32u);
        ldm4(b[1], bAddr[1] + ks * 32u);
#pragma unroll
        for (int mt = 0; mt < 2; mt++)
#pragma unroll
            for (int nt = 0; nt < 4; nt++)
                mma16816(acc[mt][nt], a[mt], &b[nt >> 1][(nt & 1) * 2]);
    }

    // ---- epilogue ----
    if (EPI == 2) {
#pragma unroll
        for (int mt = 0; mt < 2; mt++) {
#pragma unroll
            for (int h = 0; h < 2; h++) {
                int node = m0 + wm + mt * 16 + g + h * 8;
                if (node >= NR) continue;
                float dv = g_dinv[node];
#pragma unroll
                for (int nt = 0; nt < 4; nt++) {
                    int feat = n0 + wn + nt * 8 + 2 * tg;
                    if (feat >= Mout) continue;
                    float ox = fmaxf(acc[mt][nt][h * 2 + 0] + bias[feat], 0.f) * dv;
                    float oy = fmaxf(acc[mt][nt][h * 2 + 1] + bias[feat + 1], 0.f) * dv;
                    *(__half2*)&C[(size_t)node * ldc + feat] = __floats2half2_rn(ox, oy);
                }
            }
        }
    } else {  // EPI 3: maxpool over nodes (batch ids sorted)
        int nodeA = m0 + wm + g;
        bool allv = (nodeA + 24) < NR;
        bool samegraph = allv && (batch[nodeA] == batch[nodeA + 24]);
        if (samegraph) {
            int bg = batch[nodeA];
#pragma unroll
            for (int nt = 0; nt < 4; nt++) {
                int feat = n0 + wn + nt * 8 + 2 * tg;
                if (feat >= Mout) continue;
#pragma unroll
                for (int e = 0; e < 2; e++) {
                    float m = fmaxf(fmaxf(acc[0][nt][e], acc[0][nt][2 + e]),
                                    fmaxf(acc[1][nt][e], acc[1][nt][2 + e]));
                    float v = fmaxf(m + bias[feat + e], 0.f);
                    if (v > 0.f)
                        atomicMax(&pool[(size_t)bg * 312 + feat + e], __float_as_uint(v));
                }
            }
        } else {
#pragma unroll
            for (int mt = 0; mt < 2; mt++) {
#pragma unroll
                for (int h = 0; h < 2; h++) {
                    int node = m0 + wm + mt * 16 + g + h * 8;
                    if (node >= NR) continue;
                    int bg = batch[node];
#pragma unroll
                    for (int nt = 0; nt < 4; nt++) {
                        int feat = n0 + wn + nt * 8 + 2 * tg;
                        if (feat >= Mout) continue;
#pragma unroll
                        for (int e = 0; e < 2; e++) {
                            float v = fmaxf(acc[mt][nt][h * 2 + e] + bias[feat + e], 0.f);
                            if (v > 0.f)
                                atomicMax(&pool[(size_t)bg * 312 + feat + e], __float_as_uint(v));
                        }
                    }
                }
            }
        }
    }
}

// ---------------------------------------------------------------------------
// Scalar f32 SIMT GEMM (small head GEMMs): C[NR,M] = A[NR,K] @ W[K,M]
// Epilogues: 0 STORE, 1 RELU, 4 ADD_ATOMIC (split-K)
// ---------------------------------------------------------------------------
#define GBM 128
#define GBN 64
#define GBK 16

template <int EPI>
__global__ __launch_bounds__(256)
void k_gemm(const float* __restrict__ A, int lda,
            const float* __restrict__ W, int ldb,
            float* __restrict__ C, int ldc,
            int NR, int M, int K,
            const float* __restrict__ bias,
            int kChunk) {
    __shared__ float As[GBK][GBM + 4];
    __shared__ float Bs[GBK][GBN + 4];

    const int m0 = blockIdx.x * GBM;
    const int n0 = blockIdx.y * GBN;
    const int kb = blockIdx.z * kChunk;
    const int ke = min(K, kb + kChunk);

    const int tid = threadIdx.x;
    const int tN = tid & 15;
    const int tM = tid >> 4;

    float acc[8][4];
#pragma unroll
    for (int i = 0; i < 8; i++)
#pragma unroll
        for (int j = 0; j < 4; j++) acc[i][j] = 0.f;

    for (int k0 = kb; k0 < ke; k0 += GBK) {
#pragma unroll
        for (int r = 0; r < 8; r++) {
            int idx = tid + r * 256;
            int mm = idx >> 4, kk = idx & 15;
            int gm = m0 + mm, gk = k0 + kk;
            As[kk][mm] = (gm < NR && gk < ke) ? A[(size_t)gm * lda + gk] : 0.f;
        }
#pragma unroll
        for (int r = 0; r < 4; r++) {
            int idx = tid + r * 256;
            int kk = idx >> 6, nn = idx & 63;
            int gk = k0 + kk, gn = n0 + nn;
            Bs[kk][nn] = (gk < ke && gn < M) ? W[(size_t)gk * ldb + gn] : 0.f;
        }
        __syncthreads();
#pragma unroll
        for (int kk = 0; kk < GBK; kk++) {
            float4 a0 = *reinterpret_cast<const float4*>(&As[kk][tM * 8]);
            float4 a1 = *reinterpret_cast<const float4*>(&As[kk][tM * 8 + 4]);
            float4 b0 = *reinterpret_cast<const float4*>(&Bs[kk][tN * 4]);
            float a[8] = {a0.x, a0.y, a0.z, a0.w, a1.x, a1.y, a1.z, a1.w};
            float b[4] = {b0.x, b0.y, b0.z, b0.w};
#pragma unroll
            for (int i = 0; i < 8; i++)
#pragma unroll
                for (int j = 0; j < 4; j++)
                    acc[i][j] = fmaf(a[i], b[j], acc[i][j]);
        }
        __syncthreads();
    }

#pragma unroll
    for (int i = 0; i < 8; i++) {
        int row = m0 + tM * 8 + i;
        if (row >= NR) continue;
#pragma unroll
        for (int j = 0; j < 4; j++) {
            int col = n0 + tN * 4 + j;
            if (col >= M) continue;
            float v = acc[i][j];
            if (EPI == 0) {
                if (bias) v += bias[col];
                C[(size_t)row * ldc + col] = v;
            } else if (EPI == 1) {
                v += bias[col];
                C[(size_t)row * ldc + col] = fmaxf(v, 0.f);
            } else {  // 4
                if (blockIdx.z == 0 && bias) v += bias[col];
                atomicAdd(&C[(size_t)row * ldc + col], v);
            }
        }
    }
}

// ---------------------------------------------------------------------------
// Protein branch: G[b,o,k,l] = sum_i conv_w[o,i,k] * [target[b,i] == l]
// ---------------------------------------------------------------------------
__global__ void k_gbuild(const int* __restrict__ target, const float* __restrict__ conv_w) {
    __shared__ int   ts[1000];
    __shared__ float acc[256 * 26];
    const int b = blockIdx.x, tid = threadIdx.x;
    for (int i = tid; i < 1000; i += 256) ts[i] = target[b * 1000 + i];
#pragma unroll
    for (int l = 0; l < 26; l++) acc[tid * 26 + l] = 0.f;
    __syncthreads();
    const int o = tid >> 3, k = tid & 7;
    const float* wp = conv_w + o * 8000 + k;
    for (int i = 0; i < 1000; i++) {
        acc[tid * 26 + ts[i]] += wp[i * 8];
    }
    float* g = g_G + (size_t)b * 6656 + tid * 26;
#pragma unroll
    for (int l = 0; l < 26; l++) g[l] = acc[tid * 26 + l];
}

// c[b,o,h] = conv_b[o] + sum_{k,l} G[b,o,k,l] * emb[l, h+k]
__global__ void k_cconv(const float* __restrict__ emb, const float* __restrict__ conv_b) {
    __shared__ float Gs[6656];
    __shared__ float Es[26 * 128];
    const int b = blockIdx.x, tid = threadIdx.x;
    for (int i = tid; i < 6656; i += 256) Gs[i] = g_G[(size_t)b * 6656 + i];
    for (int i = tid; i < 26 * 128; i += 256) Es[i] = emb[i];
    __syncthreads();
    for (int idx = tid; idx < 3872; idx += 256) {
        int o = idx / 121, h = idx % 121;
        float s = conv_b[o];
#pragma unroll
        for (int k = 0; k < 8; k++)
#pragma unroll
            for (int l = 0; l < 26; l++)
                s += Gs[(o * 8 + k) * 26 + l] * Es[l * 128 + h + k];
        g_Cbuf[(size_t)b * 3872 + idx] = s;
    }
}

// ---------------------------------------------------------------------------
// Final projection
// ---------------------------------------------------------------------------
__global__ void k_out(const float* __restrict__ ow, const float* __restrict__ ob,
                      float* __restrict__ out, int rows) {
    int row = blockIdx.x * 8 + (threadIdx.x >> 5);
    int lane = threadIdx.x & 31;
    if (row >= rows) return;
    float s = 0.f;
    for (int j = lane; j < 512; j += 32) s += g_S2[row * 512 + j] * ow[j];
#pragma unroll
    for (int off = 16; off; off >>= 1) s += __shfl_down_sync(0xffffffffu, s, off);
    if (lane == 0) out[row] = s + ob[0];
}

// ---------------------------------------------------------------------------
// Launch
// ---------------------------------------------------------------------------
extern "C" void kernel_launch(void* const* d_in, const int* in_sizes, int n_in,
                              void* d_out, int out_size) {
    const float* x       = (const float*)d_in[0];
    const int*   ei      = (const int*)d_in[1];
    const int*   batch   = (const int*)d_in[2];
    const int*   target  = (const int*)d_in[3];
    const float* W1      = (const float*)d_in[4];
    const float* b1      = (const float*)d_in[5];
    const float* W2      = (const float*)d_in[6];
    const float* b2      = (const float*)d_in[7];
    const float* W3      = (const float*)d_in[8];
    const float* b3      = (const float*)d_in[9];
    const float* fcg1_w  = (const float*)d_in[10];
    const float* fcg1_b  = (const float*)d_in[11];
    const float* fcg2_w  = (const float*)d_in[12];
    const float* fcg2_b  = (const float*)d_in[13];
    const float* emb     = (const float*)d_in[14];
    const float* conv_w  = (const float*)d_in[15];
    const float* conv_b  = (const float*)d_in[16];
    const float* fcxt_w  = (const float*)d_in[17];
    const float* fcxt_b  = (const float*)d_in[18];
    const float* fc1_w   = (const float*)d_in[19];
    const float* fc1_b   = (const float*)d_in[20];
    const float* fc2_w   = (const float*)d_in[21];
    const float* fc2_b   = (const float*)d_in[22];
    const float* out_w   = (const float*)d_in[23];
    const float* out_b   = (const float*)d_in[24];
    float* out = (float*)d_out;

    float *bufA, *bufB, *S1, *S2, *xc, *Cbuf;
    int *cnt;
    unsigned* pool;
    cudaGetSymbolAddress((void**)&bufA, g_bufA);
    cudaGetSymbolAddress((void**)&bufB, g_bufB);
    cudaGetSymbolAddress((void**)&cnt,  g_cnt);
    cudaGetSymbolAddress((void**)&pool, g_pool);
    cudaGetSymbolAddress((void**)&S1,   g_S1);
    cudaGetSymbolAddress((void**)&S2,   g_S2);
    cudaGetSymbolAddress((void**)&xc,   g_xc);
    cudaGetSymbolAddress((void**)&Cbuf, g_Cbuf);

    __half* hA = (__half*)bufA;
    __half* hB = (__half*)bufB;

    const int N = NN, E = EE, B = BB;
    const int NB = (N + 511) / 512;
    const int MH = (N + 127) / 128;               // 1954 node tiles

    const int SM12 = 192 * 88 * 2;                // 33792
    const int SM3  = 192 * 168 * 2;               // 64512
    cudaFuncSetAttribute(k_hmma<80, 2>,  cudaFuncAttributeMaxDynamicSharedMemorySize, SM12);
    cudaFuncSetAttribute(k_hmma<160, 3>, cudaFuncAttributeMaxDynamicSharedMemorySize, SM3);

    // ---- CSR + dinv ----
    k_zero_int<<<(N + 255) / 256, 256>>>(cnt, N);
    k_count<<<(E + 255) / 256, 256>>>(ei + E, E);
    k_scan1<<<NB, 512>>>(N);
    k_scan2<<<1, 512>>>(NB);
    k_scan3<<<(N + 255) / 256, 256>>>(N, E);
    k_fill<<<(E + 255) / 256, 256>>>(ei, ei + E, E);

    // ---- GCN layers: fp16 pipeline (agg fp32-accum, HMMA GEMM) ----
    k_agg0<39, 40><<<N / 8, 256>>>(x, (__half2*)hA, N, 78);
    k_hmma<80, 2><<<dim3(2, MH), 256, SM12>>>(hA, 78, W1, 78, hB, 80, N,
                                              b1, nullptr, nullptr);
    k_agg_h<39, 40><<<N / 8, 256>>>((const __half2*)hB, (__half2*)hA, N);
    k_hmma<80, 2><<<dim3(3, MH), 256, SM12>>>(hA, 78, W2, 156, hB, 160, N,
                                              b2, nullptr, nullptr);
    k_agg_h<78, 80><<<N / 8, 256>>>((const __half2*)hB, (__half2*)hA, N);
    k_zero_u32<<<(B * 312 + 255) / 256, 256>>>(pool, B * 312);
    k_hmma<160, 3><<<dim3(5, MH), 256, SM3>>>(hA, 156, W3, 312, nullptr, 0, N,
                                              b3, batch, pool);

    // ---- graph head ----
    k_gemm<1><<<dim3(4, 16), 256>>>((const float*)pool, 312, fcg1_w, 1024, S1, 1024,
                                    B, 1024, 312, fcg1_b, 312);
    k_zero_f32<<<(B * 256 + 255) / 256, 256>>>(xc, B * 256);
    k_gemm<0><<<dim3(4, 2), 256>>>(S1, 1024, fcg2_w, 128, xc, 256,
                                   B, 128, 1024, fcg2_b, 1024);

    // ---- protein branch (alphabet-factored conv) ----
    k_gbuild<<<B, 256>>>(target, conv_w);
    k_cconv<<<B, 256>>>(emb, conv_b);
    k_gemm<4><<<dim3(4, 2, 16), 256>>>(Cbuf, 3872, fcxt_w, 128, xc + 128, 256,
                                       B, 128, 3872, fcxt_b, 242);

    // ---- fusion head ----
    k_gemm<1><<<dim3(4, 16), 256>>>(xc, 256, fc1_w, 1024, S1, 1024,
                                    B, 1024, 256, fc1_b, 256);
    k_gemm<1><<<dim3(4, 8), 256>>>(S1, 1024, fc2_w, 512, S2, 512,
                                   B, 512, 1024, fc2_b, 1024);
    k_out<<<(B + 7) / 8, 256>>>(out_w, out_b, out, B);
}